// round 4
// baseline (speedup 1.0000x reference)
#include <cuda_runtime.h>

#define NUM_G 1024
#define HID 256
#define OUTW 768
#define GRID 592   // 148 SMs x 4 CTA slots; extra CTAs exit via empty ticket

__device__ int d_batch_is64;
__device__ int d_ticket;

// Probe batch dtype (int32 vs int64 view) + reset work ticket.
__global__ void init_kernel(const int* __restrict__ b32, int n_nodes) {
    int zeros = 0;
    int base = n_nodes / 2;
    for (int i = 0; i < 64; i++)
        if (b32[base + i] == 0) zeros++;
    d_batch_is64 = (zeros > 16) ? 1 : 0;
    d_ticket = 0;
}

__device__ __forceinline__ float dot8(const float4 a, const float4 b,
                                      const float4 wa, const float4 wb) {
    return a.x * wa.x + a.y * wa.y + a.z * wa.z + a.w * wa.w
         + b.x * wb.x + b.y * wb.y + b.z * wb.z + b.w * wb.w;
}

__device__ __forceinline__ void acc_node(const float4 a, const float4 b, float wt,
                                         float4& s0, float4& s1,
                                         float4& m0, float4& m1,
                                         float4& t0, float4& t1) {
    s0.x += a.x; s0.y += a.y; s0.z += a.z; s0.w += a.w;
    s1.x += b.x; s1.y += b.y; s1.z += b.z; s1.w += b.w;
    m0.x = fmaxf(m0.x, a.x); m0.y = fmaxf(m0.y, a.y);
    m0.z = fmaxf(m0.z, a.z); m0.w = fmaxf(m0.w, a.w);
    m1.x = fmaxf(m1.x, b.x); m1.y = fmaxf(m1.y, b.y);
    m1.z = fmaxf(m1.z, b.z); m1.w = fmaxf(m1.w, b.w);
    t0.x = fmaf(a.x, wt, t0.x); t0.y = fmaf(a.y, wt, t0.y);
    t0.z = fmaf(a.z, wt, t0.z); t0.w = fmaf(a.w, wt, t0.w);
    t1.x = fmaf(b.x, wt, t1.x); t1.y = fmaf(b.y, wt, t1.y);
    t1.z = fmaf(b.z, wt, t1.z); t1.w = fmaf(b.w, wt, t1.w);
}

__global__ __launch_bounds__(256)
void ensemble_pool_kernel(const float* __restrict__ x,
                          const void* __restrict__ batch_raw,
                          const float* __restrict__ att_w,
                          const float* __restrict__ att_b,
                          float* __restrict__ out,
                          int n_nodes) {
    __shared__ float s_part[8][HID];
    __shared__ int s_bounds[2];
    __shared__ int s_g;

    const int warp = threadIdx.x >> 5;
    const int lane = threadIdx.x & 31;
    const int t = threadIdx.x;

    const float4 w0 = reinterpret_cast<const float4*>(att_w)[lane];
    const float4 w1 = reinterpret_cast<const float4*>(att_w)[lane + 32];
    const float bias = att_b[0];
    const float NEG_INF = -__int_as_float(0x7f800000);
    const int is64 = d_batch_is64;

    while (true) {
        if (t == 0) s_g = atomicAdd(&d_ticket, 1);
        __syncthreads();
        const int g = s_g;
        if (g >= NUM_G) break;

        // Segment bounds: batch is sorted, binary search (threads 0/1).
        if (t < 2) {
            const long long target = (long long)(g + t);
            const int* b32 = (const int*)batch_raw;
            const long long* b64 = (const long long*)batch_raw;
            int lo = 0, hi = n_nodes;
            while (lo < hi) {
                int mid = (lo + hi) >> 1;
                long long v = is64 ? b64[mid] : (long long)b32[mid];
                if (v < target) lo = mid + 1; else hi = mid;
            }
            s_bounds[t] = lo;
        }
        __syncthreads();
        const int start = s_bounds[0];
        const int end   = s_bounds[1];
        __syncthreads();  // s_bounds consumed before next graph overwrites

        float4 sum0 = make_float4(0.f, 0.f, 0.f, 0.f);
        float4 sum1 = make_float4(0.f, 0.f, 0.f, 0.f);
        float4 att0 = make_float4(0.f, 0.f, 0.f, 0.f);
        float4 att1 = make_float4(0.f, 0.f, 0.f, 0.f);
        float4 mx0  = make_float4(NEG_INF, NEG_INF, NEG_INF, NEG_INF);
        float4 mx1  = make_float4(NEG_INF, NEG_INF, NEG_INF, NEG_INF);

        const int total = end - start;
        const int n_main = total & ~31;       // 8 warps x 4 nodes per iter
        const int stop = start + n_main;

        // Main loop: 4 consecutive rows per warp per iteration (8 LDG.128 in flight).
        for (int base = start + (warp << 2); base < stop; base += 32) {
            const float4* r0 = reinterpret_cast<const float4*>(x + (size_t)(base + 0) * HID);
            const float4* r1 = reinterpret_cast<const float4*>(x + (size_t)(base + 1) * HID);
            const float4* r2 = reinterpret_cast<const float4*>(x + (size_t)(base + 2) * HID);
            const float4* r3 = reinterpret_cast<const float4*>(x + (size_t)(base + 3) * HID);
            const float4 a0 = r0[lane], b0 = r0[lane + 32];
            const float4 a1 = r1[lane], b1 = r1[lane + 32];
            const float4 a2 = r2[lane], b2 = r2[lane + 32];
            const float4 a3 = r3[lane], b3 = r3[lane + 32];

            float p0 = dot8(a0, b0, w0, w1);
            float p1 = dot8(a1, b1, w0, w1);
            float p2 = dot8(a2, b2, w0, w1);
            float p3 = dot8(a3, b3, w0, w1);
            #pragma unroll
            for (int off = 16; off > 0; off >>= 1) {
                p0 += __shfl_xor_sync(0xffffffffu, p0, off);
                p1 += __shfl_xor_sync(0xffffffffu, p1, off);
                p2 += __shfl_xor_sync(0xffffffffu, p2, off);
                p3 += __shfl_xor_sync(0xffffffffu, p3, off);
            }
            const float wt0 = 1.0f / (1.0f + __expf(-(p0 + bias)));
            const float wt1 = 1.0f / (1.0f + __expf(-(p1 + bias)));
            const float wt2 = 1.0f / (1.0f + __expf(-(p2 + bias)));
            const float wt3 = 1.0f / (1.0f + __expf(-(p3 + bias)));

            acc_node(a0, b0, wt0, sum0, sum1, mx0, mx1, att0, att1);
            acc_node(a1, b1, wt1, sum0, sum1, mx0, mx1, att0, att1);
            acc_node(a2, b2, wt2, sum0, sum1, mx0, mx1, att0, att1);
            acc_node(a3, b3, wt3, sum0, sum1, mx0, mx1, att0, att1);
        }

        // Remainder (< 32 nodes): one node per warp, stride 8.
        for (int node = stop + warp; node < end; node += 8) {
            const float4* row = reinterpret_cast<const float4*>(x + (size_t)node * HID);
            const float4 a = row[lane], b = row[lane + 32];
            float p = dot8(a, b, w0, w1);
            #pragma unroll
            for (int off = 16; off > 0; off >>= 1)
                p += __shfl_xor_sync(0xffffffffu, p, off);
            const float wt = 1.0f / (1.0f + __expf(-(p + bias)));
            acc_node(a, b, wt, sum0, sum1, mx0, mx1, att0, att1);
        }

        const float inv_cnt = 1.0f / fmaxf((float)total, 1.0f);
        float* orow = out + (size_t)g * OUTW;

        // --- combine SUM (mean) ---
        reinterpret_cast<float4*>(&s_part[warp][4 * lane])[0]       = sum0;
        reinterpret_cast<float4*>(&s_part[warp][128 + 4 * lane])[0] = sum1;
        __syncthreads();
        {
            float acc = 0.f;
            #pragma unroll
            for (int w = 0; w < 8; w++) acc += s_part[w][t];
            orow[t] = acc * inv_cnt;
        }
        __syncthreads();

        // --- combine MAX ---
        reinterpret_cast<float4*>(&s_part[warp][4 * lane])[0]       = mx0;
        reinterpret_cast<float4*>(&s_part[warp][128 + 4 * lane])[0] = mx1;
        __syncthreads();
        {
            float acc = NEG_INF;
            #pragma unroll
            for (int w = 0; w < 8; w++) acc = fmaxf(acc, s_part[w][t]);
            orow[HID + t] = acc;
        }
        __syncthreads();

        // --- combine ATT ---
        reinterpret_cast<float4*>(&s_part[warp][4 * lane])[0]       = att0;
        reinterpret_cast<float4*>(&s_part[warp][128 + 4 * lane])[0] = att1;
        __syncthreads();
        {
            float acc = 0.f;
            #pragma unroll
            for (int w = 0; w < 8; w++) acc += s_part[w][t];
            orow[2 * HID + t] = acc;
        }
        __syncthreads();
    }
}

extern "C" void kernel_launch(void* const* d_in, const int* in_sizes, int n_in,
                              void* d_out, int out_size) {
    const float* x     = (const float*)d_in[0];
    const void*  batch = d_in[1];
    const float* att_w = (const float*)d_in[2];
    const float* att_b = (const float*)d_in[3];
    float*       out   = (float*)d_out;
    const int n_nodes = in_sizes[1];

    init_kernel<<<1, 1>>>((const int*)batch, n_nodes);
    ensemble_pool_kernel<<<GRID, 256>>>(x, batch, att_w, att_b, out, n_nodes);
}

// round 5
// speedup vs baseline: 1.1286x; 1.1286x over previous
#include <cuda_runtime.h>
#include <cstdint>

#define NUM_G 1024
#define HID 256
#define OUTW 768
#define GRID 444   // 148 SMs x 3 resident CTAs

__device__ int d_batch_is64;
__device__ int d_ticket;

__global__ void init_kernel(const int* __restrict__ b32, int n_nodes) {
    int zeros = 0;
    int base = n_nodes / 2;
    for (int i = 0; i < 64; i++)
        if (b32[base + i] == 0) zeros++;
    d_batch_is64 = (zeros > 16) ? 1 : 0;
    d_ticket = 0;
}

__device__ __forceinline__ void cpa16(uint32_t saddr, const void* gptr) {
    asm volatile("cp.async.cg.shared.global [%0], [%1], 16;\n" :: "r"(saddr), "l"(gptr));
}
__device__ __forceinline__ void cpa_commit() {
    asm volatile("cp.async.commit_group;\n" ::: "memory");
}
template <int N> __device__ __forceinline__ void cpa_wait() {
    asm volatile("cp.async.wait_group %0;\n" :: "n"(N) : "memory");
}

__device__ __forceinline__ float dot8(const float4 a, const float4 b,
                                      const float4 wa, const float4 wb) {
    return a.x * wa.x + a.y * wa.y + a.z * wa.z + a.w * wa.w
         + b.x * wb.x + b.y * wb.y + b.z * wb.z + b.w * wb.w;
}

__device__ __forceinline__ void acc_node(const float4 a, const float4 b, float wt,
                                         float4& s0, float4& s1,
                                         float4& m0, float4& m1,
                                         float4& t0, float4& t1) {
    s0.x += a.x; s0.y += a.y; s0.z += a.z; s0.w += a.w;
    s1.x += b.x; s1.y += b.y; s1.z += b.z; s1.w += b.w;
    m0.x = fmaxf(m0.x, a.x); m0.y = fmaxf(m0.y, a.y);
    m0.z = fmaxf(m0.z, a.z); m0.w = fmaxf(m0.w, a.w);
    m1.x = fmaxf(m1.x, b.x); m1.y = fmaxf(m1.y, b.y);
    m1.z = fmaxf(m1.z, b.z); m1.w = fmaxf(m1.w, b.w);
    t0.x = fmaf(a.x, wt, t0.x); t0.y = fmaf(a.y, wt, t0.y);
    t0.z = fmaf(a.z, wt, t0.z); t0.w = fmaf(a.w, wt, t0.w);
    t1.x = fmaf(b.x, wt, t1.x); t1.y = fmaf(b.y, wt, t1.y);
    t1.z = fmaf(b.z, wt, t1.z); t1.w = fmaf(b.w, wt, t1.w);
}

__global__ __launch_bounds__(256, 3)
void ensemble_pool_kernel(const float* __restrict__ x,
                          const void* __restrict__ batch_raw,
                          const float* __restrict__ att_w,
                          const float* __restrict__ att_b,
                          float* __restrict__ out,
                          int n_nodes) {
    // 2-stage double buffer: [stage][warp][row][float4] = 2*8*2*64*16B = 32KB
    __shared__ float4 sbuf[2][8][2][64];
    __shared__ float s_part[8][HID];
    __shared__ int s_bounds[2];
    __shared__ int s_g;

    const int warp = threadIdx.x >> 5;
    const int lane = threadIdx.x & 31;
    const int t = threadIdx.x;

    const float4 w0 = reinterpret_cast<const float4*>(att_w)[lane];
    const float4 w1 = reinterpret_cast<const float4*>(att_w)[lane + 32];
    const float bias = att_b[0];
    const float NEG_INF = -__int_as_float(0x7f800000);
    const int is64 = d_batch_is64;
    const float4* x4 = reinterpret_cast<const float4*>(x);

    // Shared addresses of this lane's 4 slots per stage (lane stages & reads its own data).
    uint32_t sa[2][4];
    #pragma unroll
    for (int s = 0; s < 2; s++) {
        sa[s][0] = (uint32_t)__cvta_generic_to_shared(&sbuf[s][warp][0][lane]);
        sa[s][1] = (uint32_t)__cvta_generic_to_shared(&sbuf[s][warp][0][lane + 32]);
        sa[s][2] = (uint32_t)__cvta_generic_to_shared(&sbuf[s][warp][1][lane]);
        sa[s][3] = (uint32_t)__cvta_generic_to_shared(&sbuf[s][warp][1][lane + 32]);
    }

    while (true) {
        if (t == 0) s_g = atomicAdd(&d_ticket, 1);
        __syncthreads();
        const int g = s_g;
        if (g >= NUM_G) break;

        if (t < 2) {
            const long long target = (long long)(g + t);
            const int* b32 = (const int*)batch_raw;
            const long long* b64 = (const long long*)batch_raw;
            int lo = 0, hi = n_nodes;
            while (lo < hi) {
                int mid = (lo + hi) >> 1;
                long long v = is64 ? b64[mid] : (long long)b32[mid];
                if (v < target) lo = mid + 1; else hi = mid;
            }
            s_bounds[t] = lo;
        }
        __syncthreads();
        const int start = s_bounds[0];
        const int end   = s_bounds[1];
        __syncthreads();

        float4 sum0 = make_float4(0.f, 0.f, 0.f, 0.f);
        float4 sum1 = make_float4(0.f, 0.f, 0.f, 0.f);
        float4 att0 = make_float4(0.f, 0.f, 0.f, 0.f);
        float4 att1 = make_float4(0.f, 0.f, 0.f, 0.f);
        float4 mx0  = make_float4(NEG_INF, NEG_INF, NEG_INF, NEG_INF);
        float4 mx1  = make_float4(NEG_INF, NEG_INF, NEG_INF, NEG_INF);

        const int total = end - start;
        const int n_iter = (total & ~15) >> 4;   // 16 rows (8 warps x 2) per iter
        const int wrow0 = start + (warp << 1);   // this warp's first row for iter 0

        // Prologue: stage iter 0 into buffer 0.
        if (n_iter > 0) {
            const float4* r = x4 + (size_t)wrow0 * 64;
            cpa16(sa[0][0], r + lane);
            cpa16(sa[0][1], r + lane + 32);
            cpa16(sa[0][2], r + 64 + lane);
            cpa16(sa[0][3], r + 64 + lane + 32);
        }
        cpa_commit();

        for (int i = 0; i < n_iter; i++) {
            // Prefetch iter i+1 into the other buffer.
            const int nb = (i + 1) & 1;
            if (i + 1 < n_iter) {
                const float4* r = x4 + (size_t)(wrow0 + (i + 1) * 16) * 64;
                cpa16(sa[nb][0], r + lane);
                cpa16(sa[nb][1], r + lane + 32);
                cpa16(sa[nb][2], r + 64 + lane);
                cpa16(sa[nb][3], r + 64 + lane + 32);
            }
            cpa_commit();
            cpa_wait<1>();   // buffer for iter i ready (only newest group pending)

            const int cb = i & 1;
            const float4 a0 = sbuf[cb][warp][0][lane];
            const float4 b0 = sbuf[cb][warp][0][lane + 32];
            const float4 a1 = sbuf[cb][warp][1][lane];
            const float4 b1 = sbuf[cb][warp][1][lane + 32];

            float p0 = dot8(a0, b0, w0, w1);
            float p1 = dot8(a1, b1, w0, w1);
            #pragma unroll
            for (int off = 16; off > 0; off >>= 1) {
                p0 += __shfl_xor_sync(0xffffffffu, p0, off);
                p1 += __shfl_xor_sync(0xffffffffu, p1, off);
            }
            const float wt0 = 1.0f / (1.0f + __expf(-(p0 + bias)));
            const float wt1 = 1.0f / (1.0f + __expf(-(p1 + bias)));

            acc_node(a0, b0, wt0, sum0, sum1, mx0, mx1, att0, att1);
            acc_node(a1, b1, wt1, sum0, sum1, mx0, mx1, att0, att1);
        }
        cpa_wait<0>();  // retire all before sbuf reuse (next graph)

        // Remainder (< 16 rows): plain LDG, one node per warp.
        for (int node = start + (n_iter << 4) + warp; node < end; node += 8) {
            const float4* row = x4 + (size_t)node * 64;
            const float4 a = row[lane], b = row[lane + 32];
            float p = dot8(a, b, w0, w1);
            #pragma unroll
            for (int off = 16; off > 0; off >>= 1)
                p += __shfl_xor_sync(0xffffffffu, p, off);
            const float wt = 1.0f / (1.0f + __expf(-(p + bias)));
            acc_node(a, b, wt, sum0, sum1, mx0, mx1, att0, att1);
        }

        const float inv_cnt = 1.0f / fmaxf((float)total, 1.0f);
        float* orow = out + (size_t)g * OUTW;

        // --- combine SUM (mean) ---
        reinterpret_cast<float4*>(&s_part[warp][4 * lane])[0]       = sum0;
        reinterpret_cast<float4*>(&s_part[warp][128 + 4 * lane])[0] = sum1;
        __syncthreads();
        {
            float acc = 0.f;
            #pragma unroll
            for (int w = 0; w < 8; w++) acc += s_part[w][t];
            orow[t] = acc * inv_cnt;
        }
        __syncthreads();

        // --- combine MAX ---
        reinterpret_cast<float4*>(&s_part[warp][4 * lane])[0]       = mx0;
        reinterpret_cast<float4*>(&s_part[warp][128 + 4 * lane])[0] = mx1;
        __syncthreads();
        {
            float acc = NEG_INF;
            #pragma unroll
            for (int w = 0; w < 8; w++) acc = fmaxf(acc, s_part[w][t]);
            orow[HID + t] = acc;
        }
        __syncthreads();

        // --- combine ATT ---
        reinterpret_cast<float4*>(&s_part[warp][4 * lane])[0]       = att0;
        reinterpret_cast<float4*>(&s_part[warp][128 + 4 * lane])[0] = att1;
        __syncthreads();
        {
            float acc = 0.f;
            #pragma unroll
            for (int w = 0; w < 8; w++) acc += s_part[w][t];
            orow[2 * HID + t] = acc;
        }
        __syncthreads();
    }
}

extern "C" void kernel_launch(void* const* d_in, const int* in_sizes, int n_in,
                              void* d_out, int out_size) {
    const float* x     = (const float*)d_in[0];
    const void*  batch = d_in[1];
    const float* att_w = (const float*)d_in[2];
    const float* att_b = (const float*)d_in[3];
    float*       out   = (float*)d_out;
    const int n_nodes = in_sizes[1];

    init_kernel<<<1, 1>>>((const int*)batch, n_nodes);
    ensemble_pool_kernel<<<GRID, 256>>>(x, batch, att_w, att_b, out, n_nodes);
}

// round 6
// speedup vs baseline: 1.1289x; 1.0003x over previous
#include <cuda_runtime.h>
#include <cstdint>

#define NUM_G 1024
#define HID 256
#define OUTW 768
#define GRID 444   // 148 SMs x 3 resident CTAs

__device__ int d_batch_is64;
__device__ int d_ticket;

__global__ void init_kernel(const int* __restrict__ b32, int n_nodes) {
    int zeros = 0;
    int base = n_nodes / 2;
    for (int i = 0; i < 64; i++)
        if (b32[base + i] == 0) zeros++;
    d_batch_is64 = (zeros > 16) ? 1 : 0;
    d_ticket = 0;
}

__device__ __forceinline__ void cpa16(uint32_t saddr, const void* gptr) {
    asm volatile("cp.async.cg.shared.global [%0], [%1], 16;\n" :: "r"(saddr), "l"(gptr));
}
__device__ __forceinline__ void cpa_commit() {
    asm volatile("cp.async.commit_group;\n" ::: "memory");
}
template <int N> __device__ __forceinline__ void cpa_wait() {
    asm volatile("cp.async.wait_group %0;\n" :: "n"(N) : "memory");
}

__device__ __forceinline__ float dot8(const float4 a, const float4 b,
                                      const float4 wa, const float4 wb) {
    return a.x * wa.x + a.y * wa.y + a.z * wa.z + a.w * wa.w
         + b.x * wb.x + b.y * wb.y + b.z * wb.z + b.w * wb.w;
}

__device__ __forceinline__ void acc_node(const float4 a, const float4 b, float wt,
                                         float4& s0, float4& s1,
                                         float4& m0, float4& m1,
                                         float4& t0, float4& t1) {
    s0.x += a.x; s0.y += a.y; s0.z += a.z; s0.w += a.w;
    s1.x += b.x; s1.y += b.y; s1.z += b.z; s1.w += b.w;
    m0.x = fmaxf(m0.x, a.x); m0.y = fmaxf(m0.y, a.y);
    m0.z = fmaxf(m0.z, a.z); m0.w = fmaxf(m0.w, a.w);
    m1.x = fmaxf(m1.x, b.x); m1.y = fmaxf(m1.y, b.y);
    m1.z = fmaxf(m1.z, b.z); m1.w = fmaxf(m1.w, b.w);
    t0.x = fmaf(a.x, wt, t0.x); t0.y = fmaf(a.y, wt, t0.y);
    t0.z = fmaf(a.z, wt, t0.z); t0.w = fmaf(a.w, wt, t0.w);
    t1.x = fmaf(b.x, wt, t1.x); t1.y = fmaf(b.y, wt, t1.y);
    t1.z = fmaf(b.z, wt, t1.z); t1.w = fmaf(b.w, wt, t1.w);
}

__global__ __launch_bounds__(256, 3)
void ensemble_pool_kernel(const float* __restrict__ x,
                          const void* __restrict__ batch_raw,
                          const float* __restrict__ att_w,
                          const float* __restrict__ att_b,
                          float* __restrict__ out,
                          int n_nodes) {
    // One 48KB arena. Layout:
    //   sbuf  : 3 stages x 8 warps x 2 rows x 64 float4 = 49152B (whole arena)
    //   s_part: 8x256 floats (8KB)  — aliases stage 0 (used only post cpa_wait<0> + barrier)
    //   ctrl  : 3 ints at offset 16384 — aliases stage 1 (consumed behind a barrier
    //           before any staging writes)
    __shared__ __align__(16) unsigned char smem_raw[49152];
    typedef float4 SBuf[3][8][2][64];
    SBuf& sbuf = *reinterpret_cast<SBuf*>(smem_raw);
    typedef float SPart[8][HID];
    SPart& s_part = *reinterpret_cast<SPart*>(smem_raw);
    int* ctrl = reinterpret_cast<int*>(smem_raw + 16384); // [0]=g, [1],[2]=bounds

    const int warp = threadIdx.x >> 5;
    const int lane = threadIdx.x & 31;
    const int t = threadIdx.x;

    const float4 w0 = reinterpret_cast<const float4*>(att_w)[lane];
    const float4 w1 = reinterpret_cast<const float4*>(att_w)[lane + 32];
    const float bias = att_b[0];
    const float NEG_INF = -__int_as_float(0x7f800000);
    const int is64 = d_batch_is64;
    const float4* x4 = reinterpret_cast<const float4*>(x);

    // Shared addresses of this lane's 4 slots per stage.
    uint32_t sa[3][4];
    #pragma unroll
    for (int s = 0; s < 3; s++) {
        sa[s][0] = (uint32_t)__cvta_generic_to_shared(&sbuf[s][warp][0][lane]);
        sa[s][1] = (uint32_t)__cvta_generic_to_shared(&sbuf[s][warp][0][lane + 32]);
        sa[s][2] = (uint32_t)__cvta_generic_to_shared(&sbuf[s][warp][1][lane]);
        sa[s][3] = (uint32_t)__cvta_generic_to_shared(&sbuf[s][warp][1][lane + 32]);
    }

    while (true) {
        if (t == 0) ctrl[0] = atomicAdd(&d_ticket, 1);
        __syncthreads();
        const int g = ctrl[0];
        if (g >= NUM_G) break;

        if (t < 2) {
            const long long target = (long long)(g + t);
            const int* b32 = (const int*)batch_raw;
            const long long* b64 = (const long long*)batch_raw;
            int lo = 0, hi = n_nodes;
            while (lo < hi) {
                int mid = (lo + hi) >> 1;
                long long v = is64 ? b64[mid] : (long long)b32[mid];
                if (v < target) lo = mid + 1; else hi = mid;
            }
            ctrl[1 + t] = lo;
        }
        __syncthreads();
        const int start = ctrl[1];
        const int end   = ctrl[2];
        __syncthreads();   // everyone holds start/end in regs before staging stomps ctrl

        float4 sum0 = make_float4(0.f, 0.f, 0.f, 0.f);
        float4 sum1 = make_float4(0.f, 0.f, 0.f, 0.f);
        float4 att0 = make_float4(0.f, 0.f, 0.f, 0.f);
        float4 att1 = make_float4(0.f, 0.f, 0.f, 0.f);
        float4 mx0  = make_float4(NEG_INF, NEG_INF, NEG_INF, NEG_INF);
        float4 mx1  = make_float4(NEG_INF, NEG_INF, NEG_INF, NEG_INF);

        const int total = end - start;
        const int n_iter = (total & ~15) >> 4;   // 16 rows (8 warps x 2) per iter
        const int wrow0 = start + (warp << 1);

        // Prologue: stage iters 0 and 1 (prefetch distance 2).
        #pragma unroll
        for (int pi = 0; pi < 2; pi++) {
            if (pi < n_iter) {
                const float4* r = x4 + (size_t)(wrow0 + pi * 16) * 64;
                cpa16(sa[pi][0], r + lane);
                cpa16(sa[pi][1], r + lane + 32);
                cpa16(sa[pi][2], r + 64 + lane);
                cpa16(sa[pi][3], r + 64 + lane + 32);
            }
            cpa_commit();
        }

        for (int i = 0; i < n_iter; i++) {
            // Prefetch iter i+2 (3-stage ring).
            const int ps = (i + 2) % 3;
            if (i + 2 < n_iter) {
                const float4* r = x4 + (size_t)(wrow0 + (i + 2) * 16) * 64;
                cpa16(sa[ps][0], r + lane);
                cpa16(sa[ps][1], r + lane + 32);
                cpa16(sa[ps][2], r + 64 + lane);
                cpa16(sa[ps][3], r + 64 + lane + 32);
            }
            cpa_commit();
            cpa_wait<2>();   // <=2 groups pending -> group i complete

            const int cb = i % 3;
            const float4 a0 = sbuf[cb][warp][0][lane];
            const float4 b0 = sbuf[cb][warp][0][lane + 32];
            const float4 a1 = sbuf[cb][warp][1][lane];
            const float4 b1 = sbuf[cb][warp][1][lane + 32];

            float p0 = dot8(a0, b0, w0, w1);
            float p1 = dot8(a1, b1, w0, w1);
            #pragma unroll
            for (int off = 16; off > 0; off >>= 1) {
                p0 += __shfl_xor_sync(0xffffffffu, p0, off);
                p1 += __shfl_xor_sync(0xffffffffu, p1, off);
            }
            const float wt0 = 1.0f / (1.0f + __expf(-(p0 + bias)));
            const float wt1 = 1.0f / (1.0f + __expf(-(p1 + bias)));

            acc_node(a0, b0, wt0, sum0, sum1, mx0, mx1, att0, att1);
            acc_node(a1, b1, wt1, sum0, sum1, mx0, mx1, att0, att1);
        }
        cpa_wait<0>();   // all my groups retired before aliased epilogue use

        // Remainder (< 16 rows): plain LDG, one node per warp.
        for (int node = start + (n_iter << 4) + warp; node < end; node += 8) {
            const float4* row = x4 + (size_t)node * 64;
            const float4 a = row[lane], b = row[lane + 32];
            float p = dot8(a, b, w0, w1);
            #pragma unroll
            for (int off = 16; off > 0; off >>= 1)
                p += __shfl_xor_sync(0xffffffffu, p, off);
            const float wt = 1.0f / (1.0f + __expf(-(p + bias)));
            acc_node(a, b, wt, sum0, sum1, mx0, mx1, att0, att1);
        }
        __syncthreads();   // all warps past cpa_wait<0> before s_part aliasing writes

        const float inv_cnt = 1.0f / fmaxf((float)total, 1.0f);
        float* orow = out + (size_t)g * OUTW;

        // --- combine SUM (mean) ---
        reinterpret_cast<float4*>(&s_part[warp][4 * lane])[0]       = sum0;
        reinterpret_cast<float4*>(&s_part[warp][128 + 4 * lane])[0] = sum1;
        __syncthreads();
        {
            float acc = 0.f;
            #pragma unroll
            for (int w = 0; w < 8; w++) acc += s_part[w][t];
            orow[t] = acc * inv_cnt;
        }
        __syncthreads();

        // --- combine MAX ---
        reinterpret_cast<float4*>(&s_part[warp][4 * lane])[0]       = mx0;
        reinterpret_cast<float4*>(&s_part[warp][128 + 4 * lane])[0] = mx1;
        __syncthreads();
        {
            float acc = NEG_INF;
            #pragma unroll
            for (int w = 0; w < 8; w++) acc = fmaxf(acc, s_part[w][t]);
            orow[HID + t] = acc;
        }
        __syncthreads();

        // --- combine ATT ---
        reinterpret_cast<float4*>(&s_part[warp][4 * lane])[0]       = att0;
        reinterpret_cast<float4*>(&s_part[warp][128 + 4 * lane])[0] = att1;
        __syncthreads();
        {
            float acc = 0.f;
            #pragma unroll
            for (int w = 0; w < 8; w++) acc += s_part[w][t];
            orow[2 * HID + t] = acc;
        }
        __syncthreads();
    }
}

extern "C" void kernel_launch(void* const* d_in, const int* in_sizes, int n_in,
                              void* d_out, int out_size) {
    const float* x     = (const float*)d_in[0];
    const void*  batch = d_in[1];
    const float* att_w = (const float*)d_in[2];
    const float* att_b = (const float*)d_in[3];
    float*       out   = (float*)d_out;
    const int n_nodes = in_sizes[1];

    init_kernel<<<1, 1>>>((const int*)batch, n_nodes);
    ensemble_pool_kernel<<<GRID, 256>>>(x, batch, att_w, att_b, out, n_nodes);
}

// round 7
// speedup vs baseline: 1.2481x; 1.1056x over previous
#include <cuda_runtime.h>
#include <cstdint>

#define NUM_G 1024
#define HID 256
#define OUTW 768
#define NWARP 6
#define NTHREAD 192
#define ROWS_PER_ITER 12          // 6 warps x 2 rows
#define ITER_BYTES (ROWS_PER_ITER * HID * 4)   // 12288
#define GRID 592                  // 148 SMs x 4 CTAs

__device__ int d_batch_is64;
__device__ int d_ticket;

__global__ void init_kernel(const int* __restrict__ b32, int n_nodes) {
    int zeros = 0;
    int base = n_nodes / 2;
    for (int i = 0; i < 64; i++)
        if (b32[base + i] == 0) zeros++;
    d_batch_is64 = (zeros > 16) ? 1 : 0;
    d_ticket = 0;
}

__device__ __forceinline__ void mbar_init(uint32_t mbar, uint32_t count) {
    asm volatile("mbarrier.init.shared.b64 [%0], %1;" :: "r"(mbar), "r"(count) : "memory");
}
__device__ __forceinline__ void mbar_expect_tx(uint32_t mbar, uint32_t bytes) {
    asm volatile("mbarrier.arrive.expect_tx.shared.b64 _, [%0], %1;"
                 :: "r"(mbar), "r"(bytes) : "memory");
}
__device__ __forceinline__ void bulk_g2s(uint32_t sdst, const void* gsrc,
                                         uint32_t bytes, uint32_t mbar) {
    asm volatile("cp.async.bulk.shared::cta.global.mbarrier::complete_tx::bytes "
                 "[%0], [%1], %2, [%3];"
                 :: "r"(sdst), "l"(gsrc), "r"(bytes), "r"(mbar) : "memory");
}
__device__ __forceinline__ void mbar_wait(uint32_t mbar, uint32_t parity) {
    uint32_t done;
    asm volatile(
        "{\n\t.reg .pred p;\n\t"
        "mbarrier.try_wait.parity.acquire.cta.shared::cta.b64 p, [%1], %2;\n\t"
        "selp.b32 %0, 1, 0, p;\n\t}"
        : "=r"(done) : "r"(mbar), "r"(parity) : "memory");
    if (!done) {
        asm volatile(
            "{\n\t.reg .pred P1;\n\t"
            "WAIT_LOOP_%=:\n\t"
            "mbarrier.try_wait.parity.acquire.cta.shared::cta.b64 P1, [%0], %1, 0x989680;\n\t"
            "@P1 bra.uni WAIT_DONE_%=;\n\t"
            "bra.uni WAIT_LOOP_%=;\n\t"
            "WAIT_DONE_%=:\n\t}"
            :: "r"(mbar), "r"(parity) : "memory");
    }
}

__device__ __forceinline__ float dot8(const float4 a, const float4 b,
                                      const float4 wa, const float4 wb) {
    return a.x * wa.x + a.y * wa.y + a.z * wa.z + a.w * wa.w
         + b.x * wb.x + b.y * wb.y + b.z * wb.z + b.w * wb.w;
}

__device__ __forceinline__ void acc_node(const float4 a, const float4 b, float wt,
                                         float4& s0, float4& s1,
                                         float4& m0, float4& m1,
                                         float4& t0, float4& t1) {
    s0.x += a.x; s0.y += a.y; s0.z += a.z; s0.w += a.w;
    s1.x += b.x; s1.y += b.y; s1.z += b.z; s1.w += b.w;
    m0.x = fmaxf(m0.x, a.x); m0.y = fmaxf(m0.y, a.y);
    m0.z = fmaxf(m0.z, a.z); m0.w = fmaxf(m0.w, a.w);
    m1.x = fmaxf(m1.x, b.x); m1.y = fmaxf(m1.y, b.y);
    m1.z = fmaxf(m1.z, b.z); m1.w = fmaxf(m1.w, b.w);
    t0.x = fmaf(a.x, wt, t0.x); t0.y = fmaf(a.y, wt, t0.y);
    t0.z = fmaf(a.z, wt, t0.z); t0.w = fmaf(a.w, wt, t0.w);
    t1.x = fmaf(b.x, wt, t1.x); t1.y = fmaf(b.y, wt, t1.y);
    t1.z = fmaf(b.z, wt, t1.z); t1.w = fmaf(b.w, wt, t1.w);
}

__global__ __launch_bounds__(NTHREAD, 4)
void ensemble_pool_kernel(const float* __restrict__ x,
                          const void* __restrict__ batch_raw,
                          const float* __restrict__ att_w,
                          const float* __restrict__ att_b,
                          float* __restrict__ out,
                          int n_nodes) {
    __shared__ __align__(16) float4 sbuf[3][ROWS_PER_ITER][64];  // 36KB
    __shared__ float s_part[NWARP][HID];                          // 6KB
    __shared__ __align__(8) unsigned long long mbar_store[3];
    __shared__ int s_g, s_b0, s_b1;

    const int warp = threadIdx.x >> 5;
    const int lane = threadIdx.x & 31;
    const int t = threadIdx.x;

    const uint32_t mb0 = (uint32_t)__cvta_generic_to_shared(&mbar_store[0]);
    const uint32_t mb1 = (uint32_t)__cvta_generic_to_shared(&mbar_store[1]);
    const uint32_t mb2 = (uint32_t)__cvta_generic_to_shared(&mbar_store[2]);
    const uint32_t sd0 = (uint32_t)__cvta_generic_to_shared(&sbuf[0][0][0]);
    const uint32_t sd1 = (uint32_t)__cvta_generic_to_shared(&sbuf[1][0][0]);
    const uint32_t sd2 = (uint32_t)__cvta_generic_to_shared(&sbuf[2][0][0]);

    if (t == 0) {
        mbar_init(mb0, 1);
        mbar_init(mb1, 1);
        mbar_init(mb2, 1);
    }
    __syncthreads();

    uint32_t ph = 0;  // per-stage expected-parity bits (persist across graphs)

    const float4 w0 = reinterpret_cast<const float4*>(att_w)[lane];
    const float4 w1 = reinterpret_cast<const float4*>(att_w)[lane + 32];
    const float bias = att_b[0];
    const float NEG_INF = -__int_as_float(0x7f800000);
    const int is64 = d_batch_is64;
    const float* xf = x;

    while (true) {
        if (t == 0) s_g = atomicAdd(&d_ticket, 1);
        __syncthreads();
        const int g = s_g;
        if (g >= NUM_G) break;

        if (t < 2) {
            const long long target = (long long)(g + t);
            const int* b32 = (const int*)batch_raw;
            const long long* b64 = (const long long*)batch_raw;
            int lo = 0, hi = n_nodes;
            while (lo < hi) {
                int mid = (lo + hi) >> 1;
                long long v = is64 ? b64[mid] : (long long)b32[mid];
                if (v < target) lo = mid + 1; else hi = mid;
            }
            if (t == 0) s_b0 = lo; else s_b1 = lo;
        }
        __syncthreads();
        const int start = s_b0;
        const int end   = s_b1;

        float4 sum0 = make_float4(0.f, 0.f, 0.f, 0.f);
        float4 sum1 = make_float4(0.f, 0.f, 0.f, 0.f);
        float4 att0 = make_float4(0.f, 0.f, 0.f, 0.f);
        float4 att1 = make_float4(0.f, 0.f, 0.f, 0.f);
        float4 mx0  = make_float4(NEG_INF, NEG_INF, NEG_INF, NEG_INF);
        float4 mx1  = make_float4(NEG_INF, NEG_INF, NEG_INF, NEG_INF);

        const int total = end - start;
        const int n_iter = total / ROWS_PER_ITER;

        // Prologue: issue iters 0,1 (distance 2).
        if (t == 0) {
            if (n_iter > 0) {
                mbar_expect_tx(mb0, ITER_BYTES);
                bulk_g2s(sd0, xf + (size_t)start * HID, ITER_BYTES, mb0);
            }
            if (n_iter > 1) {
                mbar_expect_tx(mb1, ITER_BYTES);
                bulk_g2s(sd1, xf + (size_t)(start + ROWS_PER_ITER) * HID, ITER_BYTES, mb1);
            }
        }

        int s = 0;  // stage to consume
        for (int i = 0; i < n_iter; i++) {
            // Issue iter i+2 into stage (s+2)%3 (that stage was consumed in iter i-1).
            if (t == 0 && i + 2 < n_iter) {
                const int s2 = (s >= 1) ? s - 1 : 2;   // (s+2)%3
                const uint32_t mb = (s2 == 0) ? mb0 : (s2 == 1) ? mb1 : mb2;
                const uint32_t sd = (s2 == 0) ? sd0 : (s2 == 1) ? sd1 : sd2;
                mbar_expect_tx(mb, ITER_BYTES);
                bulk_g2s(sd, xf + (size_t)(start + (i + 2) * ROWS_PER_ITER) * HID,
                         ITER_BYTES, mb);
            }

            // Wait for stage s (all threads).
            const uint32_t mbw = (s == 0) ? mb0 : (s == 1) ? mb1 : mb2;
            mbar_wait(mbw, (ph >> s) & 1u);
            ph ^= (1u << s);

            const float4 a0 = sbuf[s][2 * warp][lane];
            const float4 b0 = sbuf[s][2 * warp][lane + 32];
            const float4 a1 = sbuf[s][2 * warp + 1][lane];
            const float4 b1 = sbuf[s][2 * warp + 1][lane + 32];

            float p0 = dot8(a0, b0, w0, w1);
            float p1 = dot8(a1, b1, w0, w1);
            #pragma unroll
            for (int off = 16; off > 0; off >>= 1) {
                p0 += __shfl_xor_sync(0xffffffffu, p0, off);
                p1 += __shfl_xor_sync(0xffffffffu, p1, off);
            }
            const float wt0 = 1.0f / (1.0f + __expf(-(p0 + bias)));
            const float wt1 = 1.0f / (1.0f + __expf(-(p1 + bias)));

            acc_node(a0, b0, wt0, sum0, sum1, mx0, mx1, att0, att1);
            acc_node(a1, b1, wt1, sum0, sum1, mx0, mx1, att0, att1);

            __syncthreads();   // stage s fully consumed before its reuse at i+2
            s = (s == 2) ? 0 : s + 1;
        }

        // Remainder (< 12 rows): direct LDG, one node per warp.
        for (int node = start + n_iter * ROWS_PER_ITER + warp; node < end; node += NWARP) {
            const float4* row = reinterpret_cast<const float4*>(xf + (size_t)node * HID);
            const float4 a = row[lane], b = row[lane + 32];
            float p = dot8(a, b, w0, w1);
            #pragma unroll
            for (int off = 16; off > 0; off >>= 1)
                p += __shfl_xor_sync(0xffffffffu, p, off);
            const float wt = 1.0f / (1.0f + __expf(-(p + bias)));
            acc_node(a, b, wt, sum0, sum1, mx0, mx1, att0, att1);
        }

        const float inv_cnt = 1.0f / fmaxf((float)total, 1.0f);
        float* orow = out + (size_t)g * OUTW;

        // --- combine SUM (mean) ---
        reinterpret_cast<float4*>(&s_part[warp][4 * lane])[0]       = sum0;
        reinterpret_cast<float4*>(&s_part[warp][128 + 4 * lane])[0] = sum1;
        __syncthreads();
        if (t < HID) {
            float acc = 0.f;
            #pragma unroll
            for (int w = 0; w < NWARP; w++) acc += s_part[w][t];
            orow[t] = acc * inv_cnt;
        } else {
            // threads 192..255 don't exist (192 threads); HID=256 > NTHREAD!
        }
        __syncthreads();

        // NOTE: with 192 threads, each thread handles cols t and t+192 (t<64 does 2).
        // Redo combines properly below for MAX and ATT, and fix SUM's missing cols.
        if (t < HID - NTHREAD) {   // cols 192..255 for SUM
            const int c = NTHREAD + t;
            float acc = 0.f;
            #pragma unroll
            for (int w = 0; w < NWARP; w++) acc += s_part[w][c];
            orow[c] = acc * inv_cnt;
        }
        __syncthreads();

        // --- combine MAX ---
        reinterpret_cast<float4*>(&s_part[warp][4 * lane])[0]       = mx0;
        reinterpret_cast<float4*>(&s_part[warp][128 + 4 * lane])[0] = mx1;
        __syncthreads();
        {
            float acc = NEG_INF;
            #pragma unroll
            for (int w = 0; w < NWARP; w++) acc = fmaxf(acc, s_part[w][t]);
            orow[HID + t] = acc;
            if (t < HID - NTHREAD) {
                const int c = NTHREAD + t;
                float acc2 = NEG_INF;
                #pragma unroll
                for (int w = 0; w < NWARP; w++) acc2 = fmaxf(acc2, s_part[w][c]);
                orow[HID + c] = acc2;
            }
        }
        __syncthreads();

        // --- combine ATT ---
        reinterpret_cast<float4*>(&s_part[warp][4 * lane])[0]       = att0;
        reinterpret_cast<float4*>(&s_part[warp][128 + 4 * lane])[0] = att1;
        __syncthreads();
        {
            float acc = 0.f;
            #pragma unroll
            for (int w = 0; w < NWARP; w++) acc += s_part[w][t];
            orow[2 * HID + t] = acc;
            if (t < HID - NTHREAD) {
                const int c = NTHREAD + t;
                float acc2 = 0.f;
                #pragma unroll
                for (int w = 0; w < NWARP; w++) acc2 += s_part[w][c];
                orow[2 * HID + c] = acc2;
            }
        }
        __syncthreads();
    }
}

extern "C" void kernel_launch(void* const* d_in, const int* in_sizes, int n_in,
                              void* d_out, int out_size) {
    const float* x     = (const float*)d_in[0];
    const void*  batch = d_in[1];
    const float* att_w = (const float*)d_in[2];
    const float* att_b = (const float*)d_in[3];
    float*       out   = (float*)d_out;
    const int n_nodes = in_sizes[1];

    init_kernel<<<1, 1>>>((const int*)batch, n_nodes);
    ensemble_pool_kernel<<<GRID, NTHREAD>>>(x, batch, att_w, att_b, out, n_nodes);
}